// round 8
// baseline (speedup 1.0000x reference)
#include <cuda_runtime.h>
#include <math.h>

#define NROWS 8192
#define NCOLS 8192
#define W    512               // cols per block tile (2KB per row segment)
#define BR   64                // rows per block tile
#define GX   (NCOLS / W)       // 16
#define GY   (NROWS / BR)      // 128
#define NBLK (GX * GY)         // 2048

// Scratch state. Invariant: all-zero at kernel_launch entry; the last block
// restores zeros after consuming, so every call sees identical initial state.
__device__ float g_rowsum[NROWS];
__device__ float g_colsum[NCOLS];
__device__ float g_s1part[NBLK];
__device__ unsigned int g_count;

__global__ __launch_bounds__(256) void mi_fused_kernel(const float* __restrict__ ct,
                                                       float* __restrict__ out) {
    const int tid = threadIdx.x;
    const int w   = tid >> 5;             // warp 0..7 : row owner
    const int l   = tid & 31;             // lane: 16B slot within the 2KB row segment
    const int c0  = blockIdx.x * W;
    const int r0  = blockIdx.y * BR;

    // Warp w, iteration it -> row r0 + it*8 + w.
    // Lane l loads float4 at col offsets 4l + 128j, j=0..3:
    // the warp's 4 batched LDG.128 cover ONE contiguous 2KB burst.
    const float* rowbase0 = ct + (size_t)(r0 + w) * NCOLS + c0;

    __shared__ float sp[BR][33];          // per-lane row partials (padded)

    float cacc[16];                       // col accumulators: col = 128j + 4l + m
    #pragma unroll
    for (int i = 0; i < 16; ++i) cacc[i] = 0.f;
    float s1a = 0.f, s1b = 0.f, s1c = 0.f, s1d = 0.f;

    float4 cur[4], nxt[4];
    #pragma unroll
    for (int j = 0; j < 4; ++j)
        cur[j] = __ldcs(reinterpret_cast<const float4*>(rowbase0 + 128 * j) + l);

    #pragma unroll
    for (int it = 0; it < 8; ++it) {
        if (it + 1 < 8) {
            const float* rb = rowbase0 + (size_t)(it + 1) * 8 * NCOLS;
            #pragma unroll
            for (int j = 0; j < 4; ++j)
                nxt[j] = __ldcs(reinterpret_cast<const float4*>(rb + 128 * j) + l);
        }

        float rsum = 0.f;
        #pragma unroll
        for (int j = 0; j < 4; ++j) {
            float x = cur[j].x, y = cur[j].y, z = cur[j].z, q = cur[j].w;
            // inputs >= 0; nonzero values >= 2^-24 so fmaxf(v,1e-30) == v,
            // and v==0 contributes 0 * log2(1e-30) = 0.
            s1a = __fmaf_rn(x, __log2f(fmaxf(x, 1e-30f)), s1a);
            s1b = __fmaf_rn(y, __log2f(fmaxf(y, 1e-30f)), s1b);
            s1c = __fmaf_rn(z, __log2f(fmaxf(z, 1e-30f)), s1c);
            s1d = __fmaf_rn(q, __log2f(fmaxf(q, 1e-30f)), s1d);
            cacc[j * 4 + 0] += x; cacc[j * 4 + 1] += y;
            cacc[j * 4 + 2] += z; cacc[j * 4 + 3] += q;
            rsum += (x + y) + (z + q);
        }
        sp[it * 8 + w][l] = rsum;         // no cross-lane ops in the loop

        #pragma unroll
        for (int j = 0; j < 4; ++j) cur[j] = nxt[j];
    }
    __syncthreads();

    // ---- row reduction: 4 lanes per row, 8 LDS each, 2 shuffles, 1 atomic/row ----
    {
        const int row = tid >> 2;         // 0..63
        const int q   = tid & 3;
        float t = 0.f;
        #pragma unroll
        for (int k = 0; k < 8; ++k) t += sp[row][q * 8 + k];
        t += __shfl_xor_sync(0xffffffffu, t, 1);
        t += __shfl_xor_sync(0xffffffffu, t, 2);
        if (q == 0) atomicAdd(&g_rowsum[r0 + row], t);
    }

    // ---- column reduction: one-time smem atomics across warps, then global ----
    __shared__ float scol[W];
    scol[tid] = 0.f; scol[tid + 256] = 0.f;
    __syncthreads();
    #pragma unroll
    for (int j = 0; j < 4; ++j) {
        #pragma unroll
        for (int m = 0; m < 4; ++m)
            atomicAdd(&scol[j * 128 + 4 * l + m], cacc[j * 4 + m]);
    }
    __syncthreads();
    atomicAdd(&g_colsum[c0 + tid], scol[tid]);
    atomicAdd(&g_colsum[c0 + tid + 256], scol[tid + 256]);

    // ---- S1 block partial -> plain store ----
    {
        float s1 = (s1a + s1b) + (s1c + s1d);
        #pragma unroll
        for (int o = 16; o > 0; o >>= 1)
            s1 += __shfl_xor_sync(0xffffffffu, s1, o);
        __shared__ float sw[8];
        if (l == 0) sw[w] = s1;
        __syncthreads();
        if (tid == 0) {
            float t = 0.f;
            #pragma unroll
            for (int k = 0; k < 8; ++k) t += sw[k];
            g_s1part[blockIdx.y * gridDim.x + blockIdx.x] = t;
        }
    }

    // ---- last-block completion (threadfence reduction pattern) ----
    __shared__ unsigned int is_last;
    __threadfence();
    __syncthreads();
    if (tid == 0) {
        unsigned int old = atomicAdd(&g_count, 1u);
        is_last = (old == (unsigned int)(NBLK - 1)) ? 1u : 0u;
    }
    __syncthreads();
    if (!is_last) return;

    __threadfence();  // acquire: see all blocks' writes

    double acc = 0.0;
    for (int i = tid; i < NROWS; i += 256) {
        float s = g_rowsum[i];
        if (s > 0.f) acc -= (double)s * (double)__log2f(s);
        g_rowsum[i] = 0.0f;               // restore invariant
    }
    for (int i = tid; i < NCOLS; i += 256) {
        float s = g_colsum[i];
        if (s > 0.f) acc -= (double)s * (double)__log2f(s);
        g_colsum[i] = 0.0f;               // restore invariant
    }
    for (int i = tid; i < NBLK; i += 256)
        acc += (double)g_s1part[i];       // overwritten each run, no zeroing

    #pragma unroll
    for (int o = 16; o > 0; o >>= 1)
        acc += __shfl_xor_sync(0xffffffffu, acc, o);
    __shared__ double sd[8];
    if (l == 0) sd[w] = acc;
    __syncthreads();
    if (tid == 0) {
        double a = 0.0;
        #pragma unroll
        for (int k = 0; k < 8; ++k) a += sd[k];
        out[0] = (float)a;
        g_count = 0u;                     // restore invariant
    }
}

extern "C" void kernel_launch(void* const* d_in, const int* in_sizes, int n_in,
                              void* d_out, int out_size) {
    const float* ct = (const float*)d_in[0];
    float* out = (float*)d_out;

    dim3 grid(GX, GY);
    mi_fused_kernel<<<grid, 256>>>(ct, out);
}